// round 12
// baseline (speedup 1.0000x reference)
#include <cuda_runtime.h>
#include <math.h>

#define DIMN 3
#define NPTS 30
#define KK   181
#define PP   24360          // 30*29*28
#define DE   190            // 9 + 181
#define RESTN 27
#define NTOT ((unsigned)KK * PP)   // 4,409,160 elements
#define NBIN 65536                  // bins per segment (top-16 twiddle bits)
#define NBTOT ((size_t)KK * NBIN)   // 11,862,016 bins
#define HOTCAP ((size_t)KK * (PP / 2))  // max bins with cnt>=2

// ------------------------- device scratch (static, allowed) -------------------------
// +64 floats padding: K2's cp.async prefetch of the ragged last p-tile may read
// up to 63 elements past PP in the last row; keep that inside the allocation.
__device__ __align__(16) float g_vecT[(size_t)DE * PP + 64]; // (190, P) TRANSPOSED vec
__device__ float g_wsT[190 * 192];                      // Ws_out transposed, padded
__device__ float g_wdT[RESTN * KK];                     // WdIn transposed (27, 181)
__device__ __align__(16) float g_sm2T[(size_t)KK * PP]; // (K, P) column-major sm2
__device__ __align__(16) float g_sval[(size_t)KK * PP]; // bin-ordered values
__device__ __align__(16) float g_sval2[(size_t)KK * PP];// cleanup scratch
__device__ __align__(16) unsigned int g_binA[NBTOT];    // hist -> exclusive prefix
__device__ __align__(16) unsigned int g_binB[NBTOT];    // atomic counters -> counts
__device__ unsigned int g_hot[HOTCAP];                  // bins with cnt >= 2
__device__ unsigned int g_nhot;

// ------------------------- K0: transpose Ws_out -------------------------
__global__ void k0_transpose(const float* __restrict__ WsOut) {
    int j = blockIdx.x;          // 0..189
    int t = threadIdx.x;         // 0..191
    g_wsT[j * 192 + t] = (t < KK) ? WsOut[t * DE + j] : 0.0f;
}

// ------------------------- K0b: transpose Wd_in -------------------------
__global__ void k0b_transpose(const float* __restrict__ WdIn) {
    int m = blockIdx.x;          // 0..26
    int t = threadIdx.x;         // 0..191
    if (t < KK) g_wdT[m * KK + t] = WdIn[t * RESTN + m];
}

// ------------------------- K1: per-permutation vec rows (transposed store) ------------
__global__ void k1_vec(const float* __restrict__ matrix,
                       const float* __restrict__ WsIn) {
    __shared__ float mS[DIMN * NPTS];      // 90
    __shared__ float projS[DIMN][RESTN];   // 3x27
    __shared__ float gramS[9];

    const int p = blockIdx.x;
    const int t = threadIdx.x;             // 0..191

    // decode lexicographic permutation p -> (a,b,c)
    int a  = p / 812;                // 812 = 29*28
    int r  = p - a * 812;
    int bi = r / 28;
    int ci = r - bi * 28;
    int b  = bi + (bi >= a);
    int e0 = min(a, b), e1 = max(a, b);
    int c  = ci + (ci >= e0);
    c += (c >= e1);

    // sorted excluded triple for rest[]
    int s0 = min(a, min(b, c));
    int s2 = max(a, max(b, c));
    int s1 = a + b + c - s0 - s2;

    if (t < DIMN * NPTS) mS[t] = matrix[t];
    __syncthreads();

    if (t < DIMN * RESTN) {
        int i = t / RESTN, m = t - i * RESTN;
        int rm = m + (m >= s0); rm += (rm >= s1); rm += (rm >= s2);
        int ci_ = (i == 0) ? a : ((i == 1) ? b : c);
        projS[i][m] = mS[ci_] * mS[rm]
                    + mS[NPTS + ci_] * mS[NPTS + rm]
                    + mS[2 * NPTS + ci_] * mS[2 * NPTS + rm];
    } else if (t < DIMN * RESTN + 9) {
        int q = t - DIMN * RESTN;
        int i = q / 3, j = q - 3 * i;
        int ci_ = (i == 0) ? a : ((i == 1) ? b : c);
        int cj_ = (j == 0) ? a : ((j == 1) ? b : c);
        gramS[q] = mS[ci_] * mS[cj_]
                 + mS[NPTS + ci_] * mS[NPTS + cj_]
                 + mS[2 * NPTS + ci_] * mS[2 * NPTS + cj_];
    }
    __syncthreads();

    if (t < 9) g_vecT[(size_t)t * PP + p] = gramS[t];

    if (t < KK) {
        const int k = t;
        const float w0 = WsIn[k * 3 + 0];
        const float w1 = WsIn[k * 3 + 1];
        const float w2 = WsIn[k * 3 + 2];

        float v[32];
#pragma unroll
        for (int m = 0; m < RESTN; ++m)
            v[m] = fmaf(projS[2][m], w2, fmaf(projS[1][m], w1, projS[0][m] * w0));
        const float INF = __int_as_float(0x7f800000);
#pragma unroll
        for (int m = RESTN; m < 32; ++m) v[m] = INF;

        // fully-unrolled 32-element bitonic sort (ascending), registers only
#pragma unroll
        for (int size = 2; size <= 32; size <<= 1) {
#pragma unroll
            for (int stride = size >> 1; stride > 0; stride >>= 1) {
#pragma unroll
                for (int i = 0; i < 32; ++i) {
                    int j = i ^ stride;
                    if (j > i) {
                        bool up = ((i & size) == 0);
                        float x = v[i], y = v[j];
                        float lo = fminf(x, y), hi = fmaxf(x, y);
                        v[i] = up ? lo : hi;
                        v[j] = up ? hi : lo;
                    }
                }
            }
        }

        float e = 0.0f;
#pragma unroll
        for (int m = 0; m < RESTN; ++m)
            e = fmaf(g_wdT[m * KK + k], v[m], e);   // coalesced, L1-resident
        g_vecT[(size_t)(9 + k) * PP + p] = e;
    }
}

// ------------------------- K2: sm2T[k][p] = vec[p] . Ws_out[k] -------------------------
// packed f32x2 FMA (pair along k) + cp.async double-buffered tile pipeline
#define TP 64
#define JC 19
#define NTILE (DE / JC)      // 10

__device__ __forceinline__ void ffma2(unsigned long long& d,
                                      unsigned long long a,
                                      unsigned long long b) {
    asm("fma.rn.f32x2 %0, %1, %2, %0;" : "+l"(d) : "l"(a), "l"(b));
}
__device__ __forceinline__ unsigned long long dup_f32(float x) {
    unsigned long long r;
    unsigned int u = __float_as_uint(x);
    asm("mov.b64 %0, {%1, %1};" : "=l"(r) : "r"(u));
    return r;
}
__device__ __forceinline__ void cp16(void* smem, const void* gmem) {
    unsigned int saddr = (unsigned int)__cvta_generic_to_shared(smem);
    asm volatile("cp.async.ca.shared.global [%0], [%1], 16;"
                 :: "r"(saddr), "l"(gmem));
}

__global__ void __launch_bounds__(256)
k2_gemm() {
    __shared__ __align__(16) float vS[2][JC][TP];    // 2 x 4.9 KB
    __shared__ __align__(16) float wS[2][JC][192];   // 2 x 14.6 KB

    const int p0 = blockIdx.x * TP;
    const int t  = threadIdx.x;         // 256
    const int pt = t & 15;              // 16 p-threads (4 p each)
    const int kt = t >> 4;              // 16 k-threads (12 k each = 6 pairs)

    unsigned long long acc2[4][6];      // [p][k-pair]
#pragma unroll
    for (int r0 = 0; r0 < 4; ++r0)
#pragma unroll
        for (int cc = 0; cc < 6; ++cc) acc2[r0][cc] = 0ull;

    // ---- async tile loader: tile tt (j0 = tt*JC) into buffer b ----
    auto load_tile = [&](int tt, int b) {
        const int j0 = tt * JC;
        for (int idx = t; idx < JC * TP / 4; idx += 256) {
            int row = idx >> 4;
            int col = idx & 15;
            cp16(&vS[b][row][col * 4],
                 &g_vecT[(size_t)(j0 + row) * PP + p0 + col * 4]);
        }
        for (int idx = t; idx < JC * 192 / 4; idx += 256) {
            int row = idx / 48;
            int col = idx - row * 48;
            cp16(&wS[b][row][col * 4],
                 &g_wsT[(j0 + row) * 192 + col * 4]);
        }
    };

    load_tile(0, 0);
    asm volatile("cp.async.commit_group;");

    for (int tt = 0; tt < NTILE; ++tt) {
        if (tt + 1 < NTILE) load_tile(tt + 1, (tt + 1) & 1);
        asm volatile("cp.async.commit_group;");
        asm volatile("cp.async.wait_group 1;");
        __syncthreads();

        const int b = tt & 1;
#pragma unroll
        for (int jj = 0; jj < JC; ++jj) {
            float4 rv = *reinterpret_cast<const float4*>(&vS[b][jj][pt * 4]);
            unsigned long long rr2[4] = {dup_f32(rv.x), dup_f32(rv.y),
                                         dup_f32(rv.z), dup_f32(rv.w)};
            const unsigned long long* wrow =
                reinterpret_cast<const unsigned long long*>(&wS[b][jj][0]);
            unsigned long long w2[6];
#pragma unroll
            for (int cc = 0; cc < 6; ++cc) w2[cc] = wrow[kt * 6 + cc];
#pragma unroll
            for (int cc = 0; cc < 6; ++cc)
#pragma unroll
                for (int r0 = 0; r0 < 4; ++r0)
                    ffma2(acc2[r0][cc], rr2[r0], w2[cc]);
        }
        __syncthreads();
    }

    const bool full = (p0 + TP <= PP);
#pragma unroll
    for (int cc = 0; cc < 6; ++cc) {
#pragma unroll
        for (int half = 0; half < 2; ++half) {
            int k = kt * 12 + 2 * cc + half;
            if (k >= KK) continue;
            float a0, a1, a2, a3;
            if (half == 0) {
                a0 = __uint_as_float((unsigned int)(acc2[0][cc] & 0xffffffffull));
                a1 = __uint_as_float((unsigned int)(acc2[1][cc] & 0xffffffffull));
                a2 = __uint_as_float((unsigned int)(acc2[2][cc] & 0xffffffffull));
                a3 = __uint_as_float((unsigned int)(acc2[3][cc] & 0xffffffffull));
            } else {
                a0 = __uint_as_float((unsigned int)(acc2[0][cc] >> 32));
                a1 = __uint_as_float((unsigned int)(acc2[1][cc] >> 32));
                a2 = __uint_as_float((unsigned int)(acc2[2][cc] >> 32));
                a3 = __uint_as_float((unsigned int)(acc2[3][cc] >> 32));
            }
            size_t base = (size_t)k * PP + p0 + pt * 4;
            if (full) {
                *reinterpret_cast<float4*>(&g_sm2T[base]) = make_float4(a0, a1, a2, a3);
            } else {
                float av[4] = {a0, a1, a2, a3};
#pragma unroll
                for (int r0 = 0; r0 < 4; ++r0) {
                    int p = p0 + pt * 4 + r0;
                    if (p < PP) g_sm2T[(size_t)k * PP + p] = av[r0];
                }
            }
        }
    }
}

// ------------------------- counting-sort helpers -------------------------
__device__ __forceinline__ unsigned int twiddle_u(float x) {
    unsigned int u = __float_as_uint(x);
    return (u & 0x80000000u) ? ~u : (u | 0x80000000u);
}

// K3z: zero bin arrays + hot counter
__global__ void __launch_bounds__(256)
k3z_zero() {
    size_t i = (size_t)blockIdx.x * 256 + threadIdx.x;
    size_t n4 = NBTOT / 4;
    if (i < n4) {
        reinterpret_cast<uint4*>(g_binA)[i] = make_uint4(0, 0, 0, 0);
        reinterpret_cast<uint4*>(g_binB)[i] = make_uint4(0, 0, 0, 0);
    }
    if (i == 0) g_nhot = 0;
}

// K3h: per-segment histogram of top-16 twiddle bits
__global__ void __launch_bounds__(256)
k3h_hist() {
    unsigned int i = blockIdx.x * 256 + threadIdx.x;
    if (i >= NTOT) return;
    unsigned int seg = i / PP;
    unsigned int bin = twiddle_u(g_sm2T[i]) >> 16;
    atomicAdd(&g_binA[(size_t)seg * NBIN + bin], 1u);
}

// K3s: in-place exclusive scan of each segment's 65536 bins (one block/segment)
__global__ void __launch_bounds__(1024)
k3s_scan() {
    __shared__ unsigned int warpTot[32];
    unsigned int* A = g_binA + (size_t)blockIdx.x * NBIN;
    const int t = threadIdx.x;
    const int lane = t & 31, wid = t >> 5;
    const int base = t * (NBIN / 1024);            // 64 bins per thread

    unsigned int s = 0;
#pragma unroll 8
    for (int i = 0; i < NBIN / 1024; ++i) s += A[base + i];

    // inclusive warp scan of per-thread sums
    unsigned int sc = s;
#pragma unroll
    for (int o = 1; o < 32; o <<= 1) {
        unsigned int u = __shfl_up_sync(0xffffffffu, sc, o);
        if (lane >= o) sc += u;
    }
    if (lane == 31) warpTot[wid] = sc;
    __syncthreads();
    if (t < 32) {
        unsigned int v = warpTot[t];
        unsigned int vs = v;
#pragma unroll
        for (int o = 1; o < 32; o <<= 1) {
            unsigned int u = __shfl_up_sync(0xffffffffu, vs, o);
            if (t >= o) vs += u;
        }
        warpTot[t] = vs - v;          // exclusive warp offsets
    }
    __syncthreads();

    unsigned int run = warpTot[wid] + (sc - s);    // exclusive prefix for thread
#pragma unroll 8
    for (int i = 0; i < NBIN / 1024; ++i) {
        unsigned int c = A[base + i];
        A[base + i] = run;
        run += c;
    }
}

// K3sc: scatter values to bin-ordered positions; record hot bins (cnt>=2)
__global__ void __launch_bounds__(256)
k3sc_scatter() {
    unsigned int i = blockIdx.x * 256 + threadIdx.x;
    if (i >= NTOT) return;
    float x = g_sm2T[i];
    unsigned int seg = i / PP;
    unsigned int gb = seg * NBIN + (twiddle_u(x) >> 16);
    unsigned int old = atomicAdd(&g_binB[gb], 1u);
    if (old == 1u) {                         // exactly once per bin with >=2 elems
        unsigned int pos = atomicAdd(&g_nhot, 1u);
        g_hot[pos] = gb;
    }
    unsigned int r = g_binA[gb] + old;
    g_sval[(size_t)seg * PP + r] = x;
}

// K3cl: exact warp-parallel rank sort of each hot bin run (ties by index)
__global__ void __launch_bounds__(256)
k3cl_cleanup() {
    const unsigned int gwarp = (blockIdx.x * 256 + threadIdx.x) >> 5;
    const unsigned int lane = threadIdx.x & 31;
    const unsigned int nwarp = (gridDim.x * 256) >> 5;
    const unsigned int nhot = g_nhot;

    for (unsigned int h = gwarp; h < nhot; h += nwarp) {
        unsigned int gb = g_hot[h];
        unsigned int cnt = g_binB[gb];
        unsigned int start = g_binA[gb];
        unsigned int seg = gb >> 16;
        float* v  = g_sval  + (size_t)seg * PP + start;
        float* sc = g_sval2 + (size_t)seg * PP + start;

        for (unsigned int e = lane; e < cnt; e += 32) {
            float x = v[e];
            unsigned int r = 0;
            for (unsigned int j = 0; j < cnt; ++j) {
                float y = v[j];
                r += (y < x) || (y == x && j < e);
            }
            sc[r] = x;                       // ranks form a permutation: exact
        }
        __syncwarp();
        for (unsigned int e = lane; e < cnt; e += 32) v[e] = sc[e];
        __syncwarp();
    }
}

// K3d: rank-aligned weighted dot on exactly-sorted values
__global__ void __launch_bounds__(1024)
k3d_dot(const float* __restrict__ WdOut, float* __restrict__ out) {
    __shared__ float red[32];
    const int k = blockIdx.x;
    const int t = threadIdx.x;
    const size_t base = (size_t)k * PP;

    float acc = 0.0f;
    for (int i = t; i < PP; i += 1024)
        acc = fmaf(WdOut[base + i], g_sval[base + i], acc);

#pragma unroll
    for (int o = 16; o > 0; o >>= 1)
        acc += __shfl_down_sync(0xffffffffu, acc, o);
    if ((t & 31) == 0) red[t >> 5] = acc;
    __syncthreads();
    if (t < 32) {
        float x = red[t];
#pragma unroll
        for (int o = 16; o > 0; o >>= 1)
            x += __shfl_down_sync(0xffffffffu, x, o);
        if (t == 0) out[k] = x;
    }
}

// ------------------------- launch -------------------------
extern "C" void kernel_launch(void* const* d_in, const int* in_sizes, int n_in,
                              void* d_out, int out_size) {
    const float* matrix = (const float*)d_in[0];
    const float* WsIn   = (const float*)d_in[1];
    const float* WdIn   = (const float*)d_in[2];
    const float* WsOut  = (const float*)d_in[3];
    const float* WdOut  = (const float*)d_in[4];
    float* out = (float*)d_out;

    k0_transpose<<<DE, 192>>>(WsOut);
    k0b_transpose<<<RESTN, 192>>>(WdIn);
    k1_vec<<<PP, 192>>>(matrix, WsIn);
    k2_gemm<<<(PP + TP - 1) / TP, 256>>>();

    const int eltBlocks = (int)((NTOT + 255) / 256);
    k3z_zero<<<(int)((NBTOT / 4 + 255) / 256), 256>>>();
    k3h_hist<<<eltBlocks, 256>>>();
    k3s_scan<<<KK, 1024>>>();
    k3sc_scatter<<<eltBlocks, 256>>>();
    k3cl_cleanup<<<2048, 256>>>();
    k3d_dot<<<KK, 1024>>>(WdOut, out);
}

// round 13
// speedup vs baseline: 2.3369x; 2.3369x over previous
#include <cuda_runtime.h>
#include <math.h>

#define DIMN 3
#define NPTS 30
#define KK   181
#define PP   24360          // 30*29*28
#define DE   190            // 9 + 181
#define RESTN 27
#define NBINS 8192

// dynamic smem for k3: A[PP] + B[PP] + hist[NBINS] + temps(128)
#define K3_SMEM ((2 * PP + NBINS + 128) * 4)

// ------------------------- device scratch (static, allowed) -------------------------
// +64 floats padding: K2's cp.async prefetch of the ragged last p-tile may read
// up to 63 elements past PP in the last row; keep that inside the allocation.
__device__ __align__(16) float g_vecT[(size_t)DE * PP + 64]; // (190, P) TRANSPOSED vec
__device__ float g_wsT[190 * 192];                      // Ws_out transposed, padded
__device__ float g_wdT[RESTN * KK];                     // WdIn transposed (27, 181)
__device__ __align__(16) float g_sm2T[(size_t)KK * PP]; // (K, P) column-major sm2

// ------------------------- K0: transpose Ws_out -------------------------
__global__ void k0_transpose(const float* __restrict__ WsOut) {
    int j = blockIdx.x;          // 0..189
    int t = threadIdx.x;         // 0..191
    g_wsT[j * 192 + t] = (t < KK) ? WsOut[t * DE + j] : 0.0f;
}

// ------------------------- K0b: transpose Wd_in -------------------------
__global__ void k0b_transpose(const float* __restrict__ WdIn) {
    int m = blockIdx.x;          // 0..26
    int t = threadIdx.x;         // 0..191
    if (t < KK) g_wdT[m * KK + t] = WdIn[t * RESTN + m];
}

// ------------------------- K1: per-permutation vec rows (transposed store) ------------
__global__ void k1_vec(const float* __restrict__ matrix,
                       const float* __restrict__ WsIn) {
    __shared__ float mS[DIMN * NPTS];      // 90
    __shared__ float projS[DIMN][RESTN];   // 3x27
    __shared__ float gramS[9];

    const int p = blockIdx.x;
    const int t = threadIdx.x;             // 0..191

    // decode lexicographic permutation p -> (a,b,c)
    int a  = p / 812;                // 812 = 29*28
    int r  = p - a * 812;
    int bi = r / 28;
    int ci = r - bi * 28;
    int b  = bi + (bi >= a);
    int e0 = min(a, b), e1 = max(a, b);
    int c  = ci + (ci >= e0);
    c += (c >= e1);

    // sorted excluded triple for rest[]
    int s0 = min(a, min(b, c));
    int s2 = max(a, max(b, c));
    int s1 = a + b + c - s0 - s2;

    if (t < DIMN * NPTS) mS[t] = matrix[t];
    __syncthreads();

    if (t < DIMN * RESTN) {
        int i = t / RESTN, m = t - i * RESTN;
        int rm = m + (m >= s0); rm += (rm >= s1); rm += (rm >= s2);
        int ci_ = (i == 0) ? a : ((i == 1) ? b : c);
        projS[i][m] = mS[ci_] * mS[rm]
                    + mS[NPTS + ci_] * mS[NPTS + rm]
                    + mS[2 * NPTS + ci_] * mS[2 * NPTS + rm];
    } else if (t < DIMN * RESTN + 9) {
        int q = t - DIMN * RESTN;
        int i = q / 3, j = q - 3 * i;
        int ci_ = (i == 0) ? a : ((i == 1) ? b : c);
        int cj_ = (j == 0) ? a : ((j == 1) ? b : c);
        gramS[q] = mS[ci_] * mS[cj_]
                 + mS[NPTS + ci_] * mS[NPTS + cj_]
                 + mS[2 * NPTS + ci_] * mS[2 * NPTS + cj_];
    }
    __syncthreads();

    if (t < 9) g_vecT[(size_t)t * PP + p] = gramS[t];

    if (t < KK) {
        const int k = t;
        const float w0 = WsIn[k * 3 + 0];
        const float w1 = WsIn[k * 3 + 1];
        const float w2 = WsIn[k * 3 + 2];

        float v[32];
#pragma unroll
        for (int m = 0; m < RESTN; ++m)
            v[m] = fmaf(projS[2][m], w2, fmaf(projS[1][m], w1, projS[0][m] * w0));
        const float INF = __int_as_float(0x7f800000);
#pragma unroll
        for (int m = RESTN; m < 32; ++m) v[m] = INF;

        // fully-unrolled 32-element bitonic sort (ascending), registers only
#pragma unroll
        for (int size = 2; size <= 32; size <<= 1) {
#pragma unroll
            for (int stride = size >> 1; stride > 0; stride >>= 1) {
#pragma unroll
                for (int i = 0; i < 32; ++i) {
                    int j = i ^ stride;
                    if (j > i) {
                        bool up = ((i & size) == 0);
                        float x = v[i], y = v[j];
                        float lo = fminf(x, y), hi = fmaxf(x, y);
                        v[i] = up ? lo : hi;
                        v[j] = up ? hi : lo;
                    }
                }
            }
        }

        float e = 0.0f;
#pragma unroll
        for (int m = 0; m < RESTN; ++m)
            e = fmaf(g_wdT[m * KK + k], v[m], e);   // coalesced, L1-resident
        g_vecT[(size_t)(9 + k) * PP + p] = e;
    }
}

// ------------------------- K2: sm2T[k][p] = vec[p] . Ws_out[k] -------------------------
// packed f32x2 FMA (pair along k) + cp.async double-buffered tile pipeline
#define TP 64
#define JC 19
#define NTILE (DE / JC)      // 10

__device__ __forceinline__ void ffma2(unsigned long long& d,
                                      unsigned long long a,
                                      unsigned long long b) {
    asm("fma.rn.f32x2 %0, %1, %2, %0;" : "+l"(d) : "l"(a), "l"(b));
}
__device__ __forceinline__ unsigned long long dup_f32(float x) {
    unsigned long long r;
    unsigned int u = __float_as_uint(x);
    asm("mov.b64 %0, {%1, %1};" : "=l"(r) : "r"(u));
    return r;
}
__device__ __forceinline__ void cp16(void* smem, const void* gmem) {
    unsigned int saddr = (unsigned int)__cvta_generic_to_shared(smem);
    asm volatile("cp.async.ca.shared.global [%0], [%1], 16;"
                 :: "r"(saddr), "l"(gmem));
}

__global__ void __launch_bounds__(256)
k2_gemm() {
    __shared__ __align__(16) float vS[2][JC][TP];    // 2 x 4.9 KB
    __shared__ __align__(16) float wS[2][JC][192];   // 2 x 14.6 KB

    const int p0 = blockIdx.x * TP;
    const int t  = threadIdx.x;         // 256
    const int pt = t & 15;              // 16 p-threads (4 p each)
    const int kt = t >> 4;              // 16 k-threads (12 k each = 6 pairs)

    unsigned long long acc2[4][6];      // [p][k-pair]
#pragma unroll
    for (int r0 = 0; r0 < 4; ++r0)
#pragma unroll
        for (int cc = 0; cc < 6; ++cc) acc2[r0][cc] = 0ull;

    // ---- async tile loader: tile tt (j0 = tt*JC) into buffer b ----
    auto load_tile = [&](int tt, int b) {
        const int j0 = tt * JC;
        for (int idx = t; idx < JC * TP / 4; idx += 256) {
            int row = idx >> 4;
            int col = idx & 15;
            cp16(&vS[b][row][col * 4],
                 &g_vecT[(size_t)(j0 + row) * PP + p0 + col * 4]);
        }
        for (int idx = t; idx < JC * 192 / 4; idx += 256) {
            int row = idx / 48;
            int col = idx - row * 48;
            cp16(&wS[b][row][col * 4],
                 &g_wsT[(j0 + row) * 192 + col * 4]);
        }
    };

    load_tile(0, 0);
    asm volatile("cp.async.commit_group;");

    for (int tt = 0; tt < NTILE; ++tt) {
        if (tt + 1 < NTILE) load_tile(tt + 1, (tt + 1) & 1);
        asm volatile("cp.async.commit_group;");
        asm volatile("cp.async.wait_group 1;");
        __syncthreads();

        const int b = tt & 1;
#pragma unroll
        for (int jj = 0; jj < JC; ++jj) {
            float4 rv = *reinterpret_cast<const float4*>(&vS[b][jj][pt * 4]);
            unsigned long long rr2[4] = {dup_f32(rv.x), dup_f32(rv.y),
                                         dup_f32(rv.z), dup_f32(rv.w)};
            const unsigned long long* wrow =
                reinterpret_cast<const unsigned long long*>(&wS[b][jj][0]);
            unsigned long long w2[6];
#pragma unroll
            for (int cc = 0; cc < 6; ++cc) w2[cc] = wrow[kt * 6 + cc];
#pragma unroll
            for (int cc = 0; cc < 6; ++cc)
#pragma unroll
                for (int r0 = 0; r0 < 4; ++r0)
                    ffma2(acc2[r0][cc], rr2[r0], w2[cc]);
        }
        __syncthreads();
    }

    const bool full = (p0 + TP <= PP);
#pragma unroll
    for (int cc = 0; cc < 6; ++cc) {
#pragma unroll
        for (int half = 0; half < 2; ++half) {
            int k = kt * 12 + 2 * cc + half;
            if (k >= KK) continue;
            float a0, a1, a2, a3;
            if (half == 0) {
                a0 = __uint_as_float((unsigned int)(acc2[0][cc] & 0xffffffffull));
                a1 = __uint_as_float((unsigned int)(acc2[1][cc] & 0xffffffffull));
                a2 = __uint_as_float((unsigned int)(acc2[2][cc] & 0xffffffffull));
                a3 = __uint_as_float((unsigned int)(acc2[3][cc] & 0xffffffffull));
            } else {
                a0 = __uint_as_float((unsigned int)(acc2[0][cc] >> 32));
                a1 = __uint_as_float((unsigned int)(acc2[1][cc] >> 32));
                a2 = __uint_as_float((unsigned int)(acc2[2][cc] >> 32));
                a3 = __uint_as_float((unsigned int)(acc2[3][cc] >> 32));
            }
            size_t base = (size_t)k * PP + p0 + pt * 4;
            if (full) {
                *reinterpret_cast<float4*>(&g_sm2T[base]) = make_float4(a0, a1, a2, a3);
            } else {
                float av[4] = {a0, a1, a2, a3};
#pragma unroll
                for (int r0 = 0; r0 < 4; ++r0) {
                    int p = p0 + pt * 4 + r0;
                    if (p < PP) g_sm2T[(size_t)k * PP + p] = av[r0];
                }
            }
        }
    }
}

// ------------------------- K3: in-SMEM counting sort + dot, one CTA per segment --------
__global__ void __launch_bounds__(1024)
k3_countsort(const float* __restrict__ WdOut, float* __restrict__ out) {
    extern __shared__ __align__(16) float smem[];
    float* A = smem;                                   // PP floats
    float* B = smem + PP;                              // PP floats
    unsigned int* hist = (unsigned int*)(smem + 2 * PP);  // NBINS u32
    float* wmin = (float*)(hist + NBINS);              // 32
    float* wmax = wmin + 32;                           // 32
    unsigned int* wsum = (unsigned int*)(wmax + 32);   // 32

    const int k = blockIdx.x;
    const int t = threadIdx.x;
    const int lane = t & 31, wid = t >> 5;
    const size_t gbase = (size_t)k * PP;

    // ---- load segment + min/max ----
    float mn = __int_as_float(0x7f800000), mx = -mn;
    for (int i = t; i < PP; i += 1024) {
        float x = g_sm2T[gbase + i];
        A[i] = x;
        mn = fminf(mn, x);
        mx = fmaxf(mx, x);
    }
#pragma unroll
    for (int o = 16; o > 0; o >>= 1) {
        mn = fminf(mn, __shfl_xor_sync(0xffffffffu, mn, o));
        mx = fmaxf(mx, __shfl_xor_sync(0xffffffffu, mx, o));
    }
    if (lane == 0) { wmin[wid] = mn; wmax[wid] = mx; }
    // zero hist while reduction lands
    for (int b = t; b < NBINS; b += 1024) hist[b] = 0u;
    __syncthreads();
    if (t < 32) {
        float a = wmin[t], b = wmax[t];
#pragma unroll
        for (int o = 16; o > 0; o >>= 1) {
            a = fminf(a, __shfl_xor_sync(0xffffffffu, a, o));
            b = fmaxf(b, __shfl_xor_sync(0xffffffffu, b, o));
        }
        if (t == 0) { wmin[0] = a; wmax[0] = b; }
    }
    __syncthreads();
    mn = wmin[0]; mx = wmax[0];
    const float width = mx - mn;
    const float scale = (width > 0.0f) ? (float)NBINS / width : 0.0f;
    __syncthreads();

    // ---- histogram (linear bins; same expression reused in scatter) ----
    for (int i = t; i < PP; i += 1024) {
        int bin = min(NBINS - 1, (int)((A[i] - mn) * scale));
        atomicAdd(&hist[bin], 1u);
    }
    __syncthreads();

    // ---- exclusive scan of hist (8 bins/thread) ----
    const int b8 = t * (NBINS / 1024);
    unsigned int s = 0;
#pragma unroll
    for (int i = 0; i < NBINS / 1024; ++i) s += hist[b8 + i];
    unsigned int sc = s;
#pragma unroll
    for (int o = 1; o < 32; o <<= 1) {
        unsigned int u = __shfl_up_sync(0xffffffffu, sc, o);
        if (lane >= o) sc += u;
    }
    if (lane == 31) wsum[wid] = sc;
    __syncthreads();
    if (t < 32) {
        unsigned int v = wsum[t], vs = v;
#pragma unroll
        for (int o = 1; o < 32; o <<= 1) {
            unsigned int u = __shfl_up_sync(0xffffffffu, vs, o);
            if (t >= o) vs += u;
        }
        wsum[t] = vs - v;
    }
    __syncthreads();
    unsigned int run = wsum[wid] + (sc - s);
#pragma unroll
    for (int i = 0; i < NBINS / 1024; ++i) {
        unsigned int c = hist[b8 + i];
        hist[b8 + i] = run;          // exclusive prefix (start)
        run += c;
    }
    __syncthreads();

    // ---- scatter A -> B (hist[bin] becomes end offset afterwards) ----
    for (int i = t; i < PP; i += 1024) {
        float x = A[i];
        int bin = min(NBINS - 1, (int)((x - mn) * scale));
        unsigned int pos = atomicAdd(&hist[bin], 1u);
        B[pos] = x;
    }
    __syncthreads();

    // ---- per-bin insertion sort (exact; runs are tiny for linear bins) ----
    if (scale != 0.0f) {
        for (int b = t; b < NBINS; b += 1024) {
            int e = (int)hist[b];
            int st = (b == 0) ? 0 : (int)hist[b - 1];
            for (int a2 = st + 1; a2 < e; ++a2) {
                float x = B[a2];
                int j = a2 - 1;
                while (j >= st && B[j] > x) { B[j + 1] = B[j]; --j; }
                B[j + 1] = x;
            }
        }
    }
    __syncthreads();

    // ---- rank-aligned weighted dot ----
    float acc = 0.0f;
    for (int i = t; i < PP; i += 1024)
        acc = fmaf(WdOut[gbase + i], B[i], acc);
#pragma unroll
    for (int o = 16; o > 0; o >>= 1)
        acc += __shfl_down_sync(0xffffffffu, acc, o);
    if (lane == 0) wmin[wid] = acc;
    __syncthreads();
    if (t < 32) {
        float x = wmin[t];
#pragma unroll
        for (int o = 16; o > 0; o >>= 1)
            x += __shfl_down_sync(0xffffffffu, x, o);
        if (t == 0) out[k] = x;
    }
}

// ------------------------- launch -------------------------
extern "C" void kernel_launch(void* const* d_in, const int* in_sizes, int n_in,
                              void* d_out, int out_size) {
    const float* matrix = (const float*)d_in[0];
    const float* WsIn   = (const float*)d_in[1];
    const float* WdIn   = (const float*)d_in[2];
    const float* WsOut  = (const float*)d_in[3];
    const float* WdOut  = (const float*)d_in[4];
    float* out = (float*)d_out;

    cudaFuncSetAttribute(k3_countsort, cudaFuncAttributeMaxDynamicSharedMemorySize,
                         K3_SMEM);

    k0_transpose<<<DE, 192>>>(WsOut);
    k0b_transpose<<<RESTN, 192>>>(WdIn);
    k1_vec<<<PP, 192>>>(matrix, WsIn);
    k2_gemm<<<(PP + TP - 1) / TP, 256>>>();
    k3_countsort<<<KK, 1024, K3_SMEM>>>(WdOut, out);
}